// round 1
// baseline (speedup 1.0000x reference)
#include <cuda_runtime.h>
#include <math.h>

#define NJ     140
#define NV     13059
#define NB     28
#define BATCH  512
#define KDIM   (NJ * 4)       // 560
#define NCOLS  (BATCH * 3)    // 1536

// Scratch (static device globals -- no runtime allocation allowed)
__device__ float g_B[KDIM * NCOLS];           // B matrix [560 x 1536], 3.4 MB
__device__ float g_Wv[NV * KDIM];             // A matrix [13059 x 560], 29.3 MB
__device__ float g_G[BATCH * NJ * 12];        // per-batch per-joint 3x4 transforms

// ---------------------------------------------------------------------------
// Kernel 1: kinematic chain. One thread per batch element.
// Produces: g_B (GEMM right operand, with scale+trans folded in) and J_out.
// ---------------------------------------------------------------------------
__global__ void prep_kernel(const float* __restrict__ pose,
                            const float* __restrict__ bone_len,
                            const float* __restrict__ cbl_in,
                            const float* __restrict__ trans,
                            const float* __restrict__ scale,
                            const float* __restrict__ tpj,
                            const int*   __restrict__ parent,
                            const int*   __restrict__ bone_mapper,
                            float*       __restrict__ jout)
{
    __shared__ float sJt[NJ * 3];
    __shared__ int   sPar[NJ];
    __shared__ int   sMap[NJ];
    for (int i = threadIdx.x; i < NJ * 3; i += blockDim.x) sJt[i] = tpj[i];
    for (int i = threadIdx.x; i < NJ; i += blockDim.x) {
        sPar[i] = parent[i];
        sMap[i] = bone_mapper[i];
    }
    __syncthreads();

    int b = blockIdx.x * blockDim.x + threadIdx.x;
    if (b >= BATCH) return;

    // bl = sigmoid(bone_lengths/5) * 2
    float bl[NB];
    #pragma unroll
    for (int k = 0; k < NB; k++)
        bl[k] = 2.0f / (1.0f + expf(-bone_len[b * NB + k] * 0.2f));

    float s   = scale[b];
    float cbl = cbl_in[b];
    float tr0 = trans[b * 3 + 0];
    float tr1 = trans[b * 3 + 1];
    float tr2 = trans[b * 3 + 2];

    float* Gbase = g_G + (size_t)b * NJ * 12;

    for (int j = 0; j < NJ; j++) {
        // Euler (z, y, x) -> R = Rz @ Ry @ Rx
        float ez = pose[b * NJ * 3 + j * 3 + 0];
        float ey = pose[b * NJ * 3 + j * 3 + 1];
        float ex = pose[b * NJ * 3 + j * 3 + 2];
        float cx, sx, cy, sy, cz, sz;
        sincosf(ex, &sx, &cx);
        sincosf(ey, &sy, &cy);
        sincosf(ez, &sz, &cz);
        float R[9];
        R[0] = cz * cy;  R[1] = cz * sy * sx - sz * cx;  R[2] = cz * sy * cx + sz * sx;
        R[3] = sz * cy;  R[4] = sz * sy * sx + cz * cx;  R[5] = sz * sy * cx - cz * sx;
        R[6] = -sy;      R[7] = cy * sx;                 R[8] = cy * cx;

        float Gr[9], t[3];
        if (j == 0) {
            #pragma unroll
            for (int q = 0; q < 9; q++) Gr[q] = R[q];
            t[0] = sJt[0]; t[1] = sJt[1]; t[2] = sJt[2];
        } else {
            int p = sPar[j];
            float f;
            if (j == 1) {
                f = cbl;                       // scale_per[:,0] overridden by center bone
            } else {
                int bm = sMap[j];
                f = (bm >= 0) ? bl[bm] : 1.0f;
            }
            float ob0 = (sJt[j * 3 + 0] - sJt[p * 3 + 0]) * f;
            float ob1 = (sJt[j * 3 + 1] - sJt[p * 3 + 1]) * f;
            float ob2 = (sJt[j * 3 + 2] - sJt[p * 3 + 2]) * f;

            const float* Gp = Gbase + p * 12;
            float gp[12];
            #pragma unroll
            for (int q = 0; q < 12; q++) gp[q] = Gp[q];

            #pragma unroll
            for (int r = 0; r < 3; r++) {
                #pragma unroll
                for (int c = 0; c < 3; c++) {
                    Gr[r * 3 + c] = gp[r * 3 + 0] * R[0 * 3 + c]
                                  + gp[r * 3 + 1] * R[1 * 3 + c]
                                  + gp[r * 3 + 2] * R[2 * 3 + c];
                }
                t[r] = gp[r * 3 + 0] * ob0 + gp[r * 3 + 1] * ob1
                     + gp[r * 3 + 2] * ob2 + gp[9 + r];
            }
        }

        // persist for children
        float* Gme = Gbase + j * 12;
        #pragma unroll
        for (int q = 0; q < 9; q++) Gme[q] = Gr[q];
        Gme[9] = t[0]; Gme[10] = t[1]; Gme[11] = t[2];

        // J_out = t * s + trans
        jout[b * NJ * 3 + j * 3 + 0] = t[0] * s + tr0;
        jout[b * NJ * 3 + j * 3 + 1] = t[1] * s + tr1;
        jout[b * NJ * 3 + j * 3 + 2] = t[2] * s + tr2;

        // G_rel translation: t - Gr @ Jt[j]
        float jx = sJt[j * 3 + 0], jy = sJt[j * 3 + 1], jz = sJt[j * 3 + 2];
        float gt[3];
        #pragma unroll
        for (int r = 0; r < 3; r++)
            gt[r] = t[r] - (Gr[r * 3 + 0] * jx + Gr[r * 3 + 1] * jy + Gr[r * 3 + 2] * jz);

        // Write B[k = j*4+n][col = 3b+m] = s * Grel[m][n]  (+trans[m] for n==3)
        int col = b * 3;
        #pragma unroll
        for (int m = 0; m < 3; m++) {
            float trm = (m == 0) ? tr0 : (m == 1) ? tr1 : tr2;
            #pragma unroll
            for (int n = 0; n < 4; n++) {
                float val = (n < 3) ? (Gr[m * 3 + n] * s)
                                    : (gt[m] * s + trm);
                g_B[(j * 4 + n) * NCOLS + col + m] = val;
            }
        }
    }
}

// ---------------------------------------------------------------------------
// Kernel 2: Wv[v][j*4+n] = W[v][j] * vh[v][n],  vh = (x, y, z, 1)
// ---------------------------------------------------------------------------
__global__ void wv_kernel(const float* __restrict__ W,
                          const float* __restrict__ vt)
{
    int idx = blockIdx.x * blockDim.x + threadIdx.x;
    if (idx >= NV * KDIM) return;
    int v = idx / KDIM;
    int k = idx - v * KDIM;
    int j = k >> 2;
    int n = k & 3;
    float w   = W[v * NJ + j];
    float vhn = (n == 3) ? 1.0f : vt[v * 3 + n];
    g_Wv[idx] = w * vhn;
}

// ---------------------------------------------------------------------------
// Kernel 3: SGEMM  C[13059 x 1536] = Wv[13059 x 560] @ B[560 x 1536]
// 128x128 block tile, BK=8, 8x8 per thread, scattered epilogue into
// out[b][v][m] layout (col = 3b + m).
// ---------------------------------------------------------------------------
__global__ __launch_bounds__(256, 2) void skin_gemm(float* __restrict__ out)
{
    __shared__ float As[8][128];
    __shared__ float Bs[8][128];

    int tid = threadIdx.x;
    int m0  = blockIdx.x * 128;
    int n0  = blockIdx.y * 128;
    int tx  = tid & 15;
    int ty  = tid >> 4;

    float acc[8][8];
    #pragma unroll
    for (int i = 0; i < 8; i++)
        #pragma unroll
        for (int jj = 0; jj < 8; jj++) acc[i][jj] = 0.0f;

    int arow = tid >> 1;            // 0..127
    int acol = (tid & 1) << 2;      // 0 or 4
    int brow = tid >> 5;            // 0..7
    int bcol = (tid & 31) << 2;     // 0..124

    bool avalid = (m0 + arow) < NV;
    const float* Aptr = g_Wv + (size_t)(avalid ? (m0 + arow) : 0) * KDIM + acol;
    const float* Bptr = g_B + brow * NCOLS + n0 + bcol;

    for (int k0 = 0; k0 < KDIM; k0 += 8) {
        float4 av = avalid ? *(const float4*)(Aptr + k0)
                           : make_float4(0.f, 0.f, 0.f, 0.f);
        float4 bv = *(const float4*)(Bptr + k0 * NCOLS);

        As[acol + 0][arow] = av.x;
        As[acol + 1][arow] = av.y;
        As[acol + 2][arow] = av.z;
        As[acol + 3][arow] = av.w;
        *(float4*)&Bs[brow][bcol] = bv;
        __syncthreads();

        #pragma unroll
        for (int k = 0; k < 8; k++) {
            float ra[8], rb[8];
            *(float4*)&ra[0] = *(const float4*)&As[k][ty * 4];
            *(float4*)&ra[4] = *(const float4*)&As[k][64 + ty * 4];
            *(float4*)&rb[0] = *(const float4*)&Bs[k][tx * 4];
            *(float4*)&rb[4] = *(const float4*)&Bs[k][64 + tx * 4];
            #pragma unroll
            for (int i = 0; i < 8; i++)
                #pragma unroll
                for (int jj = 0; jj < 8; jj++)
                    acc[i][jj] += ra[i] * rb[jj];
        }
        __syncthreads();
    }

    // Epilogue: C[v][n] -> out[b*NV*3 + v*3 + m], n = 3b + m
    #pragma unroll
    for (int i = 0; i < 8; i++) {
        int r = (i < 4) ? (ty * 4 + i) : (64 + ty * 4 + i - 4);
        int v = m0 + r;
        if (v >= NV) continue;
        #pragma unroll
        for (int jj = 0; jj < 8; jj++) {
            int c  = (jj < 4) ? (tx * 4 + jj) : (64 + tx * 4 + jj - 4);
            int n  = n0 + c;
            int bb = n / 3;
            int mm = n - bb * 3;
            out[(size_t)bb * (NV * 3) + v * 3 + mm] = acc[i][jj];
        }
    }
}

// ---------------------------------------------------------------------------
// Launch
// ---------------------------------------------------------------------------
extern "C" void kernel_launch(void* const* d_in, const int* in_sizes, int n_in,
                              void* d_out, int out_size)
{
    const float* pose        = (const float*)d_in[0];
    const float* bone_len    = (const float*)d_in[1];
    const float* cbl         = (const float*)d_in[2];
    const float* trans       = (const float*)d_in[3];
    const float* scale       = (const float*)d_in[4];
    const float* v_template  = (const float*)d_in[5];
    const float* tpj         = (const float*)d_in[6];
    const float* weights     = (const float*)d_in[7];
    const int*   parent      = (const int*)d_in[8];
    const int*   bone_mapper = (const int*)d_in[9];

    float* out  = (float*)d_out;
    float* jout = out + (size_t)BATCH * NV * 3;   // V first, then J_out

    prep_kernel<<<4, 128>>>(pose, bone_len, cbl, trans, scale, tpj,
                            parent, bone_mapper, jout);

    int total = NV * KDIM;
    wv_kernel<<<(total + 255) / 256, 256>>>(weights, v_template);

    dim3 grid((NV + 127) / 128, NCOLS / 128);
    skin_gemm<<<grid, 256>>>(out);
}

// round 4
// speedup vs baseline: 2.2668x; 2.2668x over previous
#include <cuda_runtime.h>
#include <math.h>

#define NJ     140
#define NV     13059
#define NB     28
#define BATCH  512
#define KDIM   (NJ * 4)       // 560
#define NCOLS  (BATCH * 3)    // 1536

// Static device scratch (no runtime allocation allowed)
__device__ float  g_B[KDIM * NCOLS];          // GEMM B [560 x 1536], 3.4 MB
__device__ float  g_Wv[NV * KDIM];            // GEMM A [13059 x 560], 29.3 MB
__device__ float4 g_R4[NJ * BATCH * 3];       // per (j,b): R(9)+off(3) in 3 float4
__device__ float4 g_H4[NJ * BATCH * 3];       // per (j,b): 3 rows of G (r0,r1,r2,t)

// ---------------------------------------------------------------------------
// Kernel 1: rotations + scaled bone offsets. One thread per (b, j).
// Layout: g_R4[(j*BATCH + b)*3 + i]
//   q0 = (R00,R01,R02,R10)  q1 = (R11,R12,R20,R21)  q2 = (R22,o0,o1,o2)
// ---------------------------------------------------------------------------
__global__ void rot_kernel(const float* __restrict__ pose,
                           const float* __restrict__ bone_len,
                           const float* __restrict__ cbl_in,
                           const float* __restrict__ tpj,
                           const int*   __restrict__ parent,
                           const int*   __restrict__ bone_mapper)
{
    int idx = blockIdx.x * blockDim.x + threadIdx.x;
    if (idx >= BATCH * NJ) return;
    int b = idx / NJ;
    int j = idx - b * NJ;

    float ez = pose[b * NJ * 3 + j * 3 + 0];
    float ey = pose[b * NJ * 3 + j * 3 + 1];
    float ex = pose[b * NJ * 3 + j * 3 + 2];
    float cx, sx, cy, sy, cz, sz;
    sincosf(ex, &sx, &cx);
    sincosf(ey, &sy, &cy);
    sincosf(ez, &sz, &cz);
    float R0 = cz * cy;
    float R1 = cz * sy * sx - sz * cx;
    float R2 = cz * sy * cx + sz * sx;
    float R3 = sz * cy;
    float R4 = sz * sy * sx + cz * cx;
    float R5 = sz * sy * cx - cz * sx;
    float R6 = -sy;
    float R7 = cy * sx;
    float R8 = cy * cx;

    float o0, o1, o2;
    if (j == 0) {
        o0 = tpj[0]; o1 = tpj[1]; o2 = tpj[2];
    } else {
        int p = parent[j];
        float f;
        if (j == 1) {
            f = cbl_in[b];
        } else {
            int bm = bone_mapper[j];
            f = (bm >= 0) ? (2.0f / (1.0f + expf(-bone_len[b * NB + bm] * 0.2f)))
                          : 1.0f;
        }
        o0 = (tpj[j * 3 + 0] - tpj[p * 3 + 0]) * f;
        o1 = (tpj[j * 3 + 1] - tpj[p * 3 + 1]) * f;
        o2 = (tpj[j * 3 + 2] - tpj[p * 3 + 2]) * f;
    }

    size_t o = (size_t)(j * BATCH + b) * 3;
    g_R4[o + 0] = make_float4(R0, R1, R2, R3);
    g_R4[o + 1] = make_float4(R4, R5, R6, R7);
    g_R4[o + 2] = make_float4(R8, o0, o1, o2);
}

// ---------------------------------------------------------------------------
// Kernel 2: kinematic chain. 3 independent lanes per batch (one per G row):
// row r of (Gp @ A) depends only on row r of Gp -> no cross-lane sync.
// FIX vs round 2: each LANE gets its own NJ-entry history buffer
//   (7 batches * 3 lanes * 140 joints * 16 B = 47,040 B shared).
// ---------------------------------------------------------------------------
#define CHAIN_BPB 7    // batches per block (3 lanes each -> 21 active threads)
__global__ __launch_bounds__(32, 1) void chain_kernel(const int* __restrict__ parent)
{
    __shared__ float4 sh[CHAIN_BPB * 3 * NJ];
    __shared__ int    sPar[NJ];

    for (int i = threadIdx.x; i < NJ; i += blockDim.x) sPar[i] = parent[i];
    __syncthreads();

    int local = threadIdx.x;
    if (local >= CHAIN_BPB * 3) return;
    int lb = local / 3;
    int r  = local - lb * 3;
    int b  = blockIdx.x * CHAIN_BPB + lb;
    if (b >= BATCH) return;

    const size_t stride = (size_t)BATCH * 3;
    const float4* Rb = g_R4 + (size_t)b * 3;        // + j*stride per joint
    float4* myhist = sh + (size_t)local * NJ;       // private per-lane history

    // ---- j = 0: G0 row r = [R[r,:], off[r]] ----
    float4 q0 = Rb[0], q1 = Rb[1], q2 = Rb[2];
    float4 row;
    if (r == 0)      row = make_float4(q0.x, q0.y, q0.z, q2.y);
    else if (r == 1) row = make_float4(q0.w, q1.x, q1.y, q2.z);
    else             row = make_float4(q1.z, q1.w, q2.x, q2.w);
    myhist[0] = row;
    g_H4[(size_t)0 * stride + b * 3 + r] = row;

    // prefetch j = 1
    float4 n0 = Rb[stride + 0];
    float4 n1 = Rb[stride + 1];
    float4 n2 = Rb[stride + 2];

    for (int j = 1; j < NJ; j++) {
        q0 = n0; q1 = n1; q2 = n2;
        if (j < NJ - 1) {
            n0 = Rb[(size_t)(j + 1) * stride + 0];
            n1 = Rb[(size_t)(j + 1) * stride + 1];
            n2 = Rb[(size_t)(j + 1) * stride + 2];
        }
        float4 hp = myhist[sPar[j]];
        float nr0 = hp.x * q0.x + hp.y * q0.w + hp.z * q1.z;        // col 0
        float nr1 = hp.x * q0.y + hp.y * q1.x + hp.z * q1.w;        // col 1
        float nr2 = hp.x * q0.z + hp.y * q1.y + hp.z * q2.x;        // col 2
        float nr3 = hp.x * q2.y + hp.y * q2.z + hp.z * q2.w + hp.w; // trans
        float4 nrow = make_float4(nr0, nr1, nr2, nr3);
        myhist[j] = nrow;
        g_H4[(size_t)j * stride + b * 3 + r] = nrow;
    }
}

// ---------------------------------------------------------------------------
// Kernel 3: G_rel + scale/trans fold -> g_B, plus J_out. One thread per (b,j).
// ---------------------------------------------------------------------------
__global__ void brel_kernel(const float* __restrict__ tpj,
                            const float* __restrict__ trans,
                            const float* __restrict__ scale,
                            float*       __restrict__ jout)
{
    int idx = blockIdx.x * blockDim.x + threadIdx.x;
    if (idx >= BATCH * NJ) return;
    int b = idx & (BATCH - 1);
    int j = idx >> 9;

    size_t base = (size_t)j * BATCH * 3 + b * 3;
    float4 h0 = g_H4[base + 0];
    float4 h1 = g_H4[base + 1];
    float4 h2 = g_H4[base + 2];

    float s   = scale[b];
    float tr0 = trans[b * 3 + 0];
    float tr1 = trans[b * 3 + 1];
    float tr2 = trans[b * 3 + 2];
    float jx = tpj[j * 3 + 0], jy = tpj[j * 3 + 1], jz = tpj[j * 3 + 2];

    jout[b * NJ * 3 + j * 3 + 0] = h0.w * s + tr0;
    jout[b * NJ * 3 + j * 3 + 1] = h1.w * s + tr1;
    jout[b * NJ * 3 + j * 3 + 2] = h2.w * s + tr2;

    float gt0 = h0.w - (h0.x * jx + h0.y * jy + h0.z * jz);
    float gt1 = h1.w - (h1.x * jx + h1.y * jy + h1.z * jz);
    float gt2 = h2.w - (h2.x * jx + h2.y * jy + h2.z * jz);

    int colb = 3 * b;
    int k = j * 4;
    g_B[(k + 0) * NCOLS + colb + 0] = h0.x * s;
    g_B[(k + 1) * NCOLS + colb + 0] = h0.y * s;
    g_B[(k + 2) * NCOLS + colb + 0] = h0.z * s;
    g_B[(k + 3) * NCOLS + colb + 0] = gt0 * s + tr0;
    g_B[(k + 0) * NCOLS + colb + 1] = h1.x * s;
    g_B[(k + 1) * NCOLS + colb + 1] = h1.y * s;
    g_B[(k + 2) * NCOLS + colb + 1] = h1.z * s;
    g_B[(k + 3) * NCOLS + colb + 1] = gt1 * s + tr1;
    g_B[(k + 0) * NCOLS + colb + 2] = h2.x * s;
    g_B[(k + 1) * NCOLS + colb + 2] = h2.y * s;
    g_B[(k + 2) * NCOLS + colb + 2] = h2.z * s;
    g_B[(k + 3) * NCOLS + colb + 2] = gt2 * s + tr2;
}

// ---------------------------------------------------------------------------
// Kernel 4: Wv[v][j*4+n] = W[v][j] * vh[v][n],  vh = (x, y, z, 1)
// ---------------------------------------------------------------------------
__global__ void wv_kernel(const float* __restrict__ W,
                          const float* __restrict__ vt)
{
    int idx = blockIdx.x * blockDim.x + threadIdx.x;
    if (idx >= NV * KDIM) return;
    int v = idx / KDIM;
    int k = idx - v * KDIM;
    int j = k >> 2;
    int n = k & 3;
    float w   = W[v * NJ + j];
    float vhn = (n == 3) ? 1.0f : vt[v * 3 + n];
    g_Wv[idx] = w * vhn;
}

// ---------------------------------------------------------------------------
// Kernel 5: SGEMM  C[13059 x 1536] = Wv[13059 x 560] @ B[560 x 1536]
// (identical to the round-1 passing version)
// ---------------------------------------------------------------------------
__global__ __launch_bounds__(256, 2) void skin_gemm(float* __restrict__ out)
{
    __shared__ float As[8][128];
    __shared__ float Bs[8][128];

    int tid = threadIdx.x;
    int m0  = blockIdx.x * 128;
    int n0  = blockIdx.y * 128;
    int tx  = tid & 15;
    int ty  = tid >> 4;

    float acc[8][8];
    #pragma unroll
    for (int i = 0; i < 8; i++)
        #pragma unroll
        for (int jj = 0; jj < 8; jj++) acc[i][jj] = 0.0f;

    int arow = tid >> 1;
    int acol = (tid & 1) << 2;
    int brow = tid >> 5;
    int bcol = (tid & 31) << 2;

    bool avalid = (m0 + arow) < NV;
    const float* Aptr = g_Wv + (size_t)(avalid ? (m0 + arow) : 0) * KDIM + acol;
    const float* Bptr = g_B + brow * NCOLS + n0 + bcol;

    for (int k0 = 0; k0 < KDIM; k0 += 8) {
        float4 av = avalid ? *(const float4*)(Aptr + k0)
                           : make_float4(0.f, 0.f, 0.f, 0.f);
        float4 bv = *(const float4*)(Bptr + k0 * NCOLS);

        As[acol + 0][arow] = av.x;
        As[acol + 1][arow] = av.y;
        As[acol + 2][arow] = av.z;
        As[acol + 3][arow] = av.w;
        *(float4*)&Bs[brow][bcol] = bv;
        __syncthreads();

        #pragma unroll
        for (int k = 0; k < 8; k++) {
            float ra[8], rb[8];
            *(float4*)&ra[0] = *(const float4*)&As[k][ty * 4];
            *(float4*)&ra[4] = *(const float4*)&As[k][64 + ty * 4];
            *(float4*)&rb[0] = *(const float4*)&Bs[k][tx * 4];
            *(float4*)&rb[4] = *(const float4*)&Bs[k][64 + tx * 4];
            #pragma unroll
            for (int i = 0; i < 8; i++)
                #pragma unroll
                for (int jj = 0; jj < 8; jj++)
                    acc[i][jj] += ra[i] * rb[jj];
        }
        __syncthreads();
    }

    #pragma unroll
    for (int i = 0; i < 8; i++) {
        int rr = (i < 4) ? (ty * 4 + i) : (64 + ty * 4 + i - 4);
        int v = m0 + rr;
        if (v >= NV) continue;
        #pragma unroll
        for (int jj = 0; jj < 8; jj++) {
            int c  = (jj < 4) ? (tx * 4 + jj) : (64 + tx * 4 + jj - 4);
            int n  = n0 + c;
            int bb = n / 3;
            int mm = n - bb * 3;
            out[(size_t)bb * (NV * 3) + v * 3 + mm] = acc[i][jj];
        }
    }
}

// ---------------------------------------------------------------------------
// Launch
// ---------------------------------------------------------------------------
extern "C" void kernel_launch(void* const* d_in, const int* in_sizes, int n_in,
                              void* d_out, int out_size)
{
    const float* pose        = (const float*)d_in[0];
    const float* bone_len    = (const float*)d_in[1];
    const float* cbl         = (const float*)d_in[2];
    const float* trans       = (const float*)d_in[3];
    const float* scale       = (const float*)d_in[4];
    const float* v_template  = (const float*)d_in[5];
    const float* tpj         = (const float*)d_in[6];
    const float* weights     = (const float*)d_in[7];
    const int*   parent      = (const int*)d_in[8];
    const int*   bone_mapper = (const int*)d_in[9];

    float* out  = (float*)d_out;
    float* jout = out + (size_t)BATCH * NV * 3;   // V first, then J_out

    int bj = BATCH * NJ;
    rot_kernel<<<(bj + 255) / 256, 256>>>(pose, bone_len, cbl, tpj,
                                          parent, bone_mapper);

    int nblk = (BATCH + CHAIN_BPB - 1) / CHAIN_BPB;
    chain_kernel<<<nblk, 32>>>(parent);

    brel_kernel<<<(bj + 255) / 256, 256>>>(tpj, trans, scale, jout);

    int total = NV * KDIM;
    wv_kernel<<<(total + 255) / 256, 256>>>(weights, v_template);

    dim3 grid((NV + 127) / 128, NCOLS / 128);
    skin_gemm<<<grid, 256>>>(out);
}

// round 7
// speedup vs baseline: 2.4235x; 1.0691x over previous
#include <cuda_runtime.h>
#include <cuda_bf16.h>
#include <math.h>
#include <stdint.h>

#define NJ     140
#define NV     13059
#define NB     28
#define BATCH  512
#define NCOLS  (BATCH * 3)       // 1536
#define PK     576               // padded K per segment
#define K3P    (3 * PK)          // 1728
#define MP     13184             // padded M (103 * 128)
#define BM     128
#define BN     192               // multiple of 3 -> 64 whole batches per tile
#define BK     32                // K elems per mainloop iter (64 B/row)
#define NIT    (K3P / BK)        // 54
#define ASTRIDE 80               // bytes per A/B smem row (64 data + 16 pad)
#define A_SMEM  (BM * ASTRIDE)   // 10240
#define B_SMEM  (BN * ASTRIDE)   // 15360
#define STG     (A_SMEM + B_SMEM)// 25600
#define CSTRIDE 195              // floats, C staging row stride
#define GEMM_SMEM_BYTES 100480   // max(2*STG=51200, 128*195*4=99840) rounded up

// Static device scratch (zero-initialized; pad regions never written => stay 0)
__device__ float4        g_R4[NJ * BATCH * 3];
__device__ float4        g_H4[NJ * BATCH * 3];
__device__ __nv_bfloat16 g_A16[(size_t)MP * K3P];     // A' [13184 x 1728]
__device__ __nv_bfloat16 g_B16[(size_t)NCOLS * K3P];  // B' [1536 x 1728]

// ---------------------------------------------------------------------------
// helpers
// ---------------------------------------------------------------------------
__device__ __forceinline__ uint32_t smem_u32(const void* p) {
    uint32_t a;
    asm("{ .reg .u64 t; cvta.to.shared.u64 t, %1; cvt.u32.u64 %0, t; }"
        : "=r"(a) : "l"(p));
    return a;
}
#define CP16(dst, src) \
    asm volatile("cp.async.cg.shared.global [%0], [%1], 16;" \
                 :: "r"(dst), "l"(src) : "memory")
#define CP_COMMIT() asm volatile("cp.async.commit_group;" ::: "memory")

__device__ __forceinline__ uint32_t pack_bf2(float a, float b) {
    __nv_bfloat162 h = __floats2bfloat162_rn(a, b);
    return *reinterpret_cast<uint32_t*>(&h);
}

__device__ __forceinline__ void ldsm4(uint32_t* r, uint32_t addr) {
    asm volatile("ldmatrix.sync.aligned.m8n8.x4.shared.b16 {%0,%1,%2,%3}, [%4];"
                 : "=r"(r[0]), "=r"(r[1]), "=r"(r[2]), "=r"(r[3]) : "r"(addr));
}
__device__ __forceinline__ void mma16816(float* d, const uint32_t* a,
                                         const uint32_t* b) {
    asm volatile(
        "mma.sync.aligned.m16n8k16.row.col.f32.bf16.bf16.f32 "
        "{%0,%1,%2,%3}, {%4,%5,%6,%7}, {%8,%9}, {%0,%1,%2,%3};"
        : "+f"(d[0]), "+f"(d[1]), "+f"(d[2]), "+f"(d[3])
        : "r"(a[0]), "r"(a[1]), "r"(a[2]), "r"(a[3]), "r"(b[0]), "r"(b[1]));
}

// ---------------------------------------------------------------------------
// Kernel 1: rotations + scaled bone offsets. One thread per (b, j).
// q0=(R00,R01,R02,R10) q1=(R11,R12,R20,R21) q2=(R22,o0,o1,o2)
// ---------------------------------------------------------------------------
__global__ void rot_kernel(const float* __restrict__ pose,
                           const float* __restrict__ bone_len,
                           const float* __restrict__ cbl_in,
                           const float* __restrict__ tpj,
                           const int*   __restrict__ parent,
                           const int*   __restrict__ bone_mapper)
{
    int idx = blockIdx.x * blockDim.x + threadIdx.x;
    if (idx >= BATCH * NJ) return;
    int b = idx / NJ;
    int j = idx - b * NJ;

    float ez = pose[b * NJ * 3 + j * 3 + 0];
    float ey = pose[b * NJ * 3 + j * 3 + 1];
    float ex = pose[b * NJ * 3 + j * 3 + 2];
    float cx, sx, cy, sy, cz, sz;
    sincosf(ex, &sx, &cx);
    sincosf(ey, &sy, &cy);
    sincosf(ez, &sz, &cz);
    float R0 = cz * cy;
    float R1 = cz * sy * sx - sz * cx;
    float R2 = cz * sy * cx + sz * sx;
    float R3 = sz * cy;
    float R4 = sz * sy * sx + cz * cx;
    float R5 = sz * sy * cx - cz * sx;
    float R6 = -sy;
    float R7 = cy * sx;
    float R8 = cy * cx;

    float o0, o1, o2;
    if (j == 0) {
        o0 = tpj[0]; o1 = tpj[1]; o2 = tpj[2];
    } else {
        int p = parent[j];
        float f;
        if (j == 1) {
            f = cbl_in[b];
        } else {
            int bm = bone_mapper[j];
            f = (bm >= 0) ? (2.0f / (1.0f + expf(-bone_len[b * NB + bm] * 0.2f)))
                          : 1.0f;
        }
        o0 = (tpj[j * 3 + 0] - tpj[p * 3 + 0]) * f;
        o1 = (tpj[j * 3 + 1] - tpj[p * 3 + 1]) * f;
        o2 = (tpj[j * 3 + 2] - tpj[p * 3 + 2]) * f;
    }

    size_t o = (size_t)(j * BATCH + b) * 3;
    g_R4[o + 0] = make_float4(R0, R1, R2, R3);
    g_R4[o + 1] = make_float4(R4, R5, R6, R7);
    g_R4[o + 2] = make_float4(R8, o0, o1, o2);
}

// ---------------------------------------------------------------------------
// Kernel 2: kinematic chain (round-4 passing version, unchanged).
// ---------------------------------------------------------------------------
#define CHAIN_BPB 7
__global__ __launch_bounds__(32, 1) void chain_kernel(const int* __restrict__ parent)
{
    __shared__ float4 sh[CHAIN_BPB * 3 * NJ];
    __shared__ int    sPar[NJ];

    for (int i = threadIdx.x; i < NJ; i += blockDim.x) sPar[i] = parent[i];
    __syncthreads();

    int local = threadIdx.x;
    if (local >= CHAIN_BPB * 3) return;
    int lb = local / 3;
    int r  = local - lb * 3;
    int b  = blockIdx.x * CHAIN_BPB + lb;
    if (b >= BATCH) return;

    const size_t stride = (size_t)BATCH * 3;
    const float4* Rb = g_R4 + (size_t)b * 3;
    float4* myhist = sh + (size_t)local * NJ;

    float4 q0 = Rb[0], q1 = Rb[1], q2 = Rb[2];
    float4 row;
    if (r == 0)      row = make_float4(q0.x, q0.y, q0.z, q2.y);
    else if (r == 1) row = make_float4(q0.w, q1.x, q1.y, q2.z);
    else             row = make_float4(q1.z, q1.w, q2.x, q2.w);
    myhist[0] = row;
    g_H4[(size_t)0 * stride + b * 3 + r] = row;

    float4 n0 = Rb[stride + 0];
    float4 n1 = Rb[stride + 1];
    float4 n2 = Rb[stride + 2];

    for (int j = 1; j < NJ; j++) {
        q0 = n0; q1 = n1; q2 = n2;
        if (j < NJ - 1) {
            n0 = Rb[(size_t)(j + 1) * stride + 0];
            n1 = Rb[(size_t)(j + 1) * stride + 1];
            n2 = Rb[(size_t)(j + 1) * stride + 2];
        }
        float4 hp = myhist[sPar[j]];
        float nr0 = hp.x * q0.x + hp.y * q0.w + hp.z * q1.z;
        float nr1 = hp.x * q0.y + hp.y * q1.x + hp.z * q1.w;
        float nr2 = hp.x * q0.z + hp.y * q1.y + hp.z * q2.x;
        float nr3 = hp.x * q2.y + hp.y * q2.z + hp.z * q2.w + hp.w;
        float4 nrow = make_float4(nr0, nr1, nr2, nr3);
        myhist[j] = nrow;
        g_H4[(size_t)j * stride + b * 3 + r] = nrow;
    }
}

// ---------------------------------------------------------------------------
// Kernel 3: G_rel fold -> g_B16 (bf16 hi/lo, segments [hi | lo | hi]) + jout.
// ---------------------------------------------------------------------------
__global__ void bt16_kernel(const float* __restrict__ tpj,
                            const float* __restrict__ trans,
                            const float* __restrict__ scale,
                            float*       __restrict__ jout)
{
    int idx = blockIdx.x * blockDim.x + threadIdx.x;
    if (idx >= BATCH * NJ) return;
    int b = idx & (BATCH - 1);
    int j = idx >> 9;

    size_t base = (size_t)j * BATCH * 3 + b * 3;
    float4 h0 = g_H4[base + 0];
    float4 h1 = g_H4[base + 1];
    float4 h2 = g_H4[base + 2];

    float s   = scale[b];
    float tr0 = trans[b * 3 + 0];
    float tr1 = trans[b * 3 + 1];
    float tr2 = trans[b * 3 + 2];
    float jx = tpj[j * 3 + 0], jy = tpj[j * 3 + 1], jz = tpj[j * 3 + 2];

    jout[b * NJ * 3 + j * 3 + 0] = h0.w * s + tr0;
    jout[b * NJ * 3 + j * 3 + 1] = h1.w * s + tr1;
    jout[b * NJ * 3 + j * 3 + 2] = h2.w * s + tr2;

    float gt0 = h0.w - (h0.x * jx + h0.y * jy + h0.z * jz);
    float gt1 = h1.w - (h1.x * jx + h1.y * jy + h1.z * jz);
    float gt2 = h2.w - (h2.x * jx + h2.y * jy + h2.z * jz);

    #pragma unroll
    for (int m = 0; m < 3; m++) {
        float4 h  = (m == 0) ? h0 : (m == 1) ? h1 : h2;
        float  gt = (m == 0) ? gt0 : (m == 1) ? gt1 : gt2;
        float  tr = (m == 0) ? tr0 : (m == 1) ? tr1 : tr2;
        float v0 = h.x * s, v1 = h.y * s, v2 = h.z * s, v3 = gt * s + tr;

        uint2 hv, lv;
        hv.x = pack_bf2(v0, v1);
        hv.y = pack_bf2(v2, v3);
        __nv_bfloat162* hp0 = reinterpret_cast<__nv_bfloat162*>(&hv.x);
        __nv_bfloat162* hp1 = reinterpret_cast<__nv_bfloat162*>(&hv.y);
        float l0 = v0 - __bfloat162float(hp0->x);
        float l1 = v1 - __bfloat162float(hp0->y);
        float l2 = v2 - __bfloat162float(hp1->x);
        float l3 = v3 - __bfloat162float(hp1->y);
        lv.x = pack_bf2(l0, l1);
        lv.y = pack_bf2(l2, l3);

        size_t rb = (size_t)(3 * b + m) * K3P + 4 * j;
        *(uint2*)(g_B16 + rb)          = hv;   // seg0: hi
        *(uint2*)(g_B16 + rb + PK)     = lv;   // seg1: lo
        *(uint2*)(g_B16 + rb + 2 * PK) = hv;   // seg2: hi
    }
}

// ---------------------------------------------------------------------------
// Kernel 4: A' = Wv in bf16 hi/lo, segments [hi | hi | lo].
// ---------------------------------------------------------------------------
__global__ void wv16_kernel(const float* __restrict__ W,
                            const float* __restrict__ vt)
{
    int idx = blockIdx.x * blockDim.x + threadIdx.x;
    if (idx >= NV * 144) return;
    int v  = idx / 144;
    int k4 = idx - v * 144;

    float v0 = 0.f, v1 = 0.f, v2 = 0.f, v3 = 0.f;
    if (k4 < NJ) {
        float w = W[v * NJ + k4];
        v0 = w * vt[v * 3 + 0];
        v1 = w * vt[v * 3 + 1];
        v2 = w * vt[v * 3 + 2];
        v3 = w;
    }
    uint2 hv, lv;
    hv.x = pack_bf2(v0, v1);
    hv.y = pack_bf2(v2, v3);
    __nv_bfloat162* hp0 = reinterpret_cast<__nv_bfloat162*>(&hv.x);
    __nv_bfloat162* hp1 = reinterpret_cast<__nv_bfloat162*>(&hv.y);
    float l0 = v0 - __bfloat162float(hp0->x);
    float l1 = v1 - __bfloat162float(hp0->y);
    float l2 = v2 - __bfloat162float(hp1->x);
    float l3 = v3 - __bfloat162float(hp1->y);
    lv.x = pack_bf2(l0, l1);
    lv.y = pack_bf2(l2, l3);

    size_t base = (size_t)v * K3P + 4 * k4;
    *(uint2*)(g_A16 + base)          = hv;   // seg0: hi
    *(uint2*)(g_A16 + base + PK)     = hv;   // seg1: hi
    *(uint2*)(g_A16 + base + 2 * PK) = lv;   // seg2: lo
}

// ---------------------------------------------------------------------------
// Kernel 5: bf16 mma.sync GEMM.  D[128 x 192] per CTA, K = 1728.
// cp.async double-buffered, ldmatrix operands, coalesced smem-staged epilogue.
// ---------------------------------------------------------------------------
__device__ __forceinline__ void load_stage(int it, uint32_t stg_base,
                                           int tid, int m0, int n0)
{
    int k0 = it * BK;
    const __nv_bfloat16* Asrc = g_A16 + (size_t)m0 * K3P + k0;
    const __nv_bfloat16* Bsrc = g_B16 + (size_t)n0 * K3P + k0;
    #pragma unroll
    for (int i = 0; i < 5; i++) {             // 1280 chunks / 256 threads
        int c = tid + i * 256;
        if (c < 512) {                        // A: 128 rows x 4 chunks
            int row = c >> 2, seg = c & 3;
            CP16(stg_base + row * ASTRIDE + seg * 16,
                 (uint64_t)__cvta_generic_to_global(
                     (const char*)(Asrc + (size_t)row * K3P) + seg * 16));
        } else {                              // B: 192 rows x 4 chunks
            int c2 = c - 512;
            int row = c2 >> 2, seg = c2 & 3;
            CP16(stg_base + A_SMEM + row * ASTRIDE + seg * 16,
                 (uint64_t)__cvta_generic_to_global(
                     (const char*)(Bsrc + (size_t)row * K3P) + seg * 16));
        }
    }
}

__global__ __launch_bounds__(256, 1) void skin_gemm_mma(float* __restrict__ out)
{
    extern __shared__ char smem[];
    uint32_t sbase = smem_u32(smem);
    int tid = threadIdx.x;
    int wid = tid >> 5;
    int lid = tid & 31;
    int wm  = wid & 1;          // 0..1 -> 64 rows each
    int wn  = wid >> 1;         // 0..3 -> 48 cols each
    int m0  = blockIdx.x * BM;
    int n0  = blockIdx.y * BN;

    float d[4][6][4];
    #pragma unroll
    for (int i = 0; i < 4; i++)
        #pragma unroll
        for (int j = 0; j < 6; j++)
            #pragma unroll
            for (int q = 0; q < 4; q++) d[i][j][q] = 0.0f;

    load_stage(0, sbase, tid, m0, n0);
    CP_COMMIT();

    // precomputed lane addressing
    int a_row = wm * 64 + (lid & 15);               // + i*16
    int a_kof = (lid >> 4) * 16;                    // bytes (+kstep*32)
    int b_row = wn * 48 + (lid & 7) + ((lid >> 4) << 3);  // + jp*16
    int b_kof = ((lid >> 3) & 1) * 16;              // bytes (+kstep*32)

    for (int it = 0; it < NIT; it++) {
        uint32_t cur = sbase + (uint32_t)(it & 1) * STG;
        if (it + 1 < NIT) {
            load_stage(it + 1, sbase + (uint32_t)((it + 1) & 1) * STG, tid, m0, n0);
            CP_COMMIT();
            asm volatile("cp.async.wait_group 1;" ::: "memory");
        } else {
            asm volatile("cp.async.wait_group 0;" ::: "memory");
        }
        __syncthreads();

        uint32_t Abase = cur;
        uint32_t Bbase = cur + A_SMEM;

        #pragma unroll
        for (int ks = 0; ks < 2; ks++) {
            uint32_t af[4][4], bf[6][2];
            #pragma unroll
            for (int i = 0; i < 4; i++)
                ldsm4(af[i], Abase + (a_row + i * 16) * ASTRIDE
                              + ks * 32 + a_kof);
            #pragma unroll
            for (int jp = 0; jp < 3; jp++) {
                uint32_t r[4];
                ldsm4(r, Bbase + (b_row + jp * 16) * ASTRIDE
                          + ks * 32 + b_kof);
                bf[2 * jp + 0][0] = r[0]; bf[2 * jp + 0][1] = r[1];
                bf[2 * jp + 1][0] = r[2]; bf[2 * jp + 1][1] = r[3];
            }
            #pragma unroll
            for (int i = 0; i < 4; i++)
                #pragma unroll
                for (int j = 0; j < 6; j++)
                    mma16816(d[i][j], af[i], bf[j]);
        }
        __syncthreads();
    }

    // ---- epilogue: stage C in smem, then coalesced scatter ----
    float* Csm = (float*)smem;
    int group = lid >> 2;
    int t4    = lid & 3;
    #pragma unroll
    for (int i = 0; i < 4; i++) {
        int r0 = wm * 64 + i * 16 + group;
        #pragma unroll
        for (int j = 0; j < 6; j++) {
            int c0 = wn * 48 + j * 8 + t4 * 2;
            Csm[r0 * CSTRIDE + c0]           = d[i][j][0];
            Csm[r0 * CSTRIDE + c0 + 1]       = d[i][j][1];
            Csm[(r0 + 8) * CSTRIDE + c0]     = d[i][j][2];
            Csm[(r0 + 8) * CSTRIDE + c0 + 1] = d[i][j][3];
        }
    }
    __syncthreads();

    int bb0 = blockIdx.y * 64;   // first batch of this tile (BN=192 = 64 batches)
    for (int e = tid; e < BM * BN; e += 256) {
        int bb  = e / 384;                 // 384 = 128 rows? no: 3*128 out-elems per batch chunk
        int rem = e - bb * 384;
        int vl  = rem / 3;
        int mm  = rem - vl * 3;
        int v   = m0 + vl;
        if (v < NV)
            out[(size_t)(bb0 + bb) * (NV * 3) + v * 3 + mm] =
                Csm[vl * CSTRIDE + bb * 3 + mm];
    }
}

// ---------------------------------------------------------------------------
// Launch
// ---------------------------------------------------------------------------
extern "C" void kernel_launch(void* const* d_in, const int* in_sizes, int n_in,
                              void* d_out, int out_size)
{
    const float* pose        = (const float*)d_in[0];
    const float* bone_len    = (const float*)d_in[1];
    const float* cbl         = (const float*)d_in[2];
    const float* trans       = (const float*)d_in[3];
    const float* scale       = (const float*)d_in[4];
    const float* v_template  = (const float*)d_in[5];
    const float* tpj         = (const float*)d_in[6];
    const float* weights     = (const float*)d_in[7];
    const int*   parent      = (const int*)d_in[8];
    const int*   bone_mapper = (const int*)d_in[9];

    float* out  = (float*)d_out;
    float* jout = out + (size_t)BATCH * NV * 3;   // V first, then J_out

    int bj = BATCH * NJ;
    rot_kernel<<<(bj + 255) / 256, 256>>>(pose, bone_len, cbl, tpj,
                                          parent, bone_mapper);

    int nblk = (BATCH + CHAIN_BPB - 1) / CHAIN_BPB;
    chain_kernel<<<nblk, 32>>>(parent);

    bt16_kernel<<<(bj + 255) / 256, 256>>>(tpj, trans, scale, jout);

    int wvt = NV * 144;
    wv16_kernel<<<(wvt + 255) / 256, 256>>>(weights, v_template);

    cudaFuncSetAttribute(skin_gemm_mma,
                         cudaFuncAttributeMaxDynamicSharedMemorySize,
                         GEMM_SMEM_BYTES);
    dim3 grid(MP / BM, NCOLS / BN);   // 103 x 8
    skin_gemm_mma<<<grid, 256, GEMM_SMEM_BYTES>>>(out);
}

// round 8
// speedup vs baseline: 4.2106x; 1.7373x over previous
#include <cuda_runtime.h>
#include <cuda_bf16.h>
#include <math.h>
#include <stdint.h>

#define NJ     140
#define NV     13059
#define NB     28
#define BATCH  512
#define NCOLS  (BATCH * 3)       // 1536
#define PK     576               // padded K per segment
#define K3P    (3 * PK)          // 1728
#define MP     13184             // padded M (103 * 128)
#define BM     128
#define BN     192               // multiple of 3 -> 64 whole batches per tile
#define BK     64                // K elems per mainloop iter (128 B/row)
#define NIT    (K3P / BK)        // 27
#define ASTRIDE 144              // bytes per smem row (128 data + 16 pad)
#define A_SMEM  (BM * ASTRIDE)   // 18432
#define B_SMEM  (BN * ASTRIDE)   // 27648
#define STG     (A_SMEM + B_SMEM)// 46080
#define CSTRIDE 195              // floats, C staging row stride (half tile: 64 rows)
#define GEMM_SMEM_BYTES (2 * STG) // 92160 (epilogue half-tile = 49920 fits)

// Static device scratch (zero-initialized; pad regions never written => stay 0)
__device__ float4        g_R4[NJ * BATCH * 3];
__device__ float4        g_H4[NJ * BATCH * 3];
__device__ __nv_bfloat16 g_A16[(size_t)MP * K3P];     // A' [13184 x 1728]
__device__ __nv_bfloat16 g_B16[(size_t)NCOLS * K3P];  // B' [1536 x 1728]

// ---------------------------------------------------------------------------
// helpers
// ---------------------------------------------------------------------------
__device__ __forceinline__ uint32_t smem_u32(const void* p) {
    uint32_t a;
    asm("{ .reg .u64 t; cvta.to.shared.u64 t, %1; cvt.u32.u64 %0, t; }"
        : "=r"(a) : "l"(p));
    return a;
}
#define CP16(dst, src) \
    asm volatile("cp.async.cg.shared.global [%0], [%1], 16;" \
                 :: "r"(dst), "l"(src) : "memory")
#define CP_COMMIT() asm volatile("cp.async.commit_group;" ::: "memory")

__device__ __forceinline__ uint32_t pack_bf2(float a, float b) {
    __nv_bfloat162 h = __floats2bfloat162_rn(a, b);
    return *reinterpret_cast<uint32_t*>(&h);
}

__device__ __forceinline__ void ldsm4(uint32_t* r, uint32_t addr) {
    asm volatile("ldmatrix.sync.aligned.m8n8.x4.shared.b16 {%0,%1,%2,%3}, [%4];"
                 : "=r"(r[0]), "=r"(r[1]), "=r"(r[2]), "=r"(r[3]) : "r"(addr));
}
__device__ __forceinline__ void mma16816(float* d, const uint32_t* a,
                                         const uint32_t* b) {
    asm volatile(
        "mma.sync.aligned.m16n8k16.row.col.f32.bf16.bf16.f32 "
        "{%0,%1,%2,%3}, {%4,%5,%6,%7}, {%8,%9}, {%0,%1,%2,%3};"
        : "+f"(d[0]), "+f"(d[1]), "+f"(d[2]), "+f"(d[3])
        : "r"(a[0]), "r"(a[1]), "r"(a[2]), "r"(a[3]), "r"(b[0]), "r"(b[1]));
}

// ---------------------------------------------------------------------------
// Kernel 1: rotations + scaled bone offsets. One thread per (b, j).
// q0=(R00,R01,R02,R10) q1=(R11,R12,R20,R21) q2=(R22,o0,o1,o2)
// ---------------------------------------------------------------------------
__global__ void rot_kernel(const float* __restrict__ pose,
                           const float* __restrict__ bone_len,
                           const float* __restrict__ cbl_in,
                           const float* __restrict__ tpj,
                           const int*   __restrict__ parent,
                           const int*   __restrict__ bone_mapper)
{
    int idx = blockIdx.x * blockDim.x + threadIdx.x;
    if (idx >= BATCH * NJ) return;
    int b = idx / NJ;
    int j = idx - b * NJ;

    float ez = pose[b * NJ * 3 + j * 3 + 0];
    float ey = pose[b * NJ * 3 + j * 3 + 1];
    float ex = pose[b * NJ * 3 + j * 3 + 2];
    float cx, sx, cy, sy, cz, sz;
    sincosf(ex, &sx, &cx);
    sincosf(ey, &sy, &cy);
    sincosf(ez, &sz, &cz);
    float R0 = cz * cy;
    float R1 = cz * sy * sx - sz * cx;
    float R2 = cz * sy * cx + sz * sx;
    float R3 = sz * cy;
    float R4 = sz * sy * sx + cz * cx;
    float R5 = sz * sy * cx - cz * sx;
    float R6 = -sy;
    float R7 = cy * sx;
    float R8 = cy * cx;

    float o0, o1, o2;
    if (j == 0) {
        o0 = tpj[0]; o1 = tpj[1]; o2 = tpj[2];
    } else {
        int p = parent[j];
        float f;
        if (j == 1) {
            f = cbl_in[b];
        } else {
            int bm = bone_mapper[j];
            f = (bm >= 0) ? (2.0f / (1.0f + expf(-bone_len[b * NB + bm] * 0.2f)))
                          : 1.0f;
        }
        o0 = (tpj[j * 3 + 0] - tpj[p * 3 + 0]) * f;
        o1 = (tpj[j * 3 + 1] - tpj[p * 3 + 1]) * f;
        o2 = (tpj[j * 3 + 2] - tpj[p * 3 + 2]) * f;
    }

    size_t o = (size_t)(j * BATCH + b) * 3;
    g_R4[o + 0] = make_float4(R0, R1, R2, R3);
    g_R4[o + 1] = make_float4(R4, R5, R6, R7);
    g_R4[o + 2] = make_float4(R8, o0, o1, o2);
}

// ---------------------------------------------------------------------------
// Kernel 2: kinematic chain (round-4 passing version, unchanged).
// ---------------------------------------------------------------------------
#define CHAIN_BPB 7
__global__ __launch_bounds__(32, 1) void chain_kernel(const int* __restrict__ parent)
{
    __shared__ float4 sh[CHAIN_BPB * 3 * NJ];
    __shared__ int    sPar[NJ];

    for (int i = threadIdx.x; i < NJ; i += blockDim.x) sPar[i] = parent[i];
    __syncthreads();

    int local = threadIdx.x;
    if (local >= CHAIN_BPB * 3) return;
    int lb = local / 3;
    int r  = local - lb * 3;
    int b  = blockIdx.x * CHAIN_BPB + lb;
    if (b >= BATCH) return;

    const size_t stride = (size_t)BATCH * 3;
    const float4* Rb = g_R4 + (size_t)b * 3;
    float4* myhist = sh + (size_t)local * NJ;

    float4 q0 = Rb[0], q1 = Rb[1], q2 = Rb[2];
    float4 row;
    if (r == 0)      row = make_float4(q0.x, q0.y, q0.z, q2.y);
    else if (r == 1) row = make_float4(q0.w, q1.x, q1.y, q2.z);
    else             row = make_float4(q1.z, q1.w, q2.x, q2.w);
    myhist[0] = row;
    g_H4[(size_t)0 * stride + b * 3 + r] = row;

    float4 n0 = Rb[stride + 0];
    float4 n1 = Rb[stride + 1];
    float4 n2 = Rb[stride + 2];

    for (int j = 1; j < NJ; j++) {
        q0 = n0; q1 = n1; q2 = n2;
        if (j < NJ - 1) {
            n0 = Rb[(size_t)(j + 1) * stride + 0];
            n1 = Rb[(size_t)(j + 1) * stride + 1];
            n2 = Rb[(size_t)(j + 1) * stride + 2];
        }
        float4 hp = myhist[sPar[j]];
        float nr0 = hp.x * q0.x + hp.y * q0.w + hp.z * q1.z;
        float nr1 = hp.x * q0.y + hp.y * q1.x + hp.z * q1.w;
        float nr2 = hp.x * q0.z + hp.y * q1.y + hp.z * q2.x;
        float nr3 = hp.x * q2.y + hp.y * q2.z + hp.z * q2.w + hp.w;
        float4 nrow = make_float4(nr0, nr1, nr2, nr3);
        myhist[j] = nrow;
        g_H4[(size_t)j * stride + b * 3 + r] = nrow;
    }
}

// ---------------------------------------------------------------------------
// Kernel 3: G_rel fold -> g_B16 (bf16 hi/lo, segments [hi | lo | hi]) + jout.
// ---------------------------------------------------------------------------
__global__ void bt16_kernel(const float* __restrict__ tpj,
                            const float* __restrict__ trans,
                            const float* __restrict__ scale,
                            float*       __restrict__ jout)
{
    int idx = blockIdx.x * blockDim.x + threadIdx.x;
    if (idx >= BATCH * NJ) return;
    int b = idx & (BATCH - 1);
    int j = idx >> 9;

    size_t base = (size_t)j * BATCH * 3 + b * 3;
    float4 h0 = g_H4[base + 0];
    float4 h1 = g_H4[base + 1];
    float4 h2 = g_H4[base + 2];

    float s   = scale[b];
    float tr0 = trans[b * 3 + 0];
    float tr1 = trans[b * 3 + 1];
    float tr2 = trans[b * 3 + 2];
    float jx = tpj[j * 3 + 0], jy = tpj[j * 3 + 1], jz = tpj[j * 3 + 2];

    jout[b * NJ * 3 + j * 3 + 0] = h0.w * s + tr0;
    jout[b * NJ * 3 + j * 3 + 1] = h1.w * s + tr1;
    jout[b * NJ * 3 + j * 3 + 2] = h2.w * s + tr2;

    float gt0 = h0.w - (h0.x * jx + h0.y * jy + h0.z * jz);
    float gt1 = h1.w - (h1.x * jx + h1.y * jy + h1.z * jz);
    float gt2 = h2.w - (h2.x * jx + h2.y * jy + h2.z * jz);

    #pragma unroll
    for (int m = 0; m < 3; m++) {
        float4 h  = (m == 0) ? h0 : (m == 1) ? h1 : h2;
        float  gt = (m == 0) ? gt0 : (m == 1) ? gt1 : gt2;
        float  tr = (m == 0) ? tr0 : (m == 1) ? tr1 : tr2;
        float v0 = h.x * s, v1 = h.y * s, v2 = h.z * s, v3 = gt * s + tr;

        uint2 hv, lv;
        hv.x = pack_bf2(v0, v1);
        hv.y = pack_bf2(v2, v3);
        __nv_bfloat162* hp0 = reinterpret_cast<__nv_bfloat162*>(&hv.x);
        __nv_bfloat162* hp1 = reinterpret_cast<__nv_bfloat162*>(&hv.y);
        float l0 = v0 - __bfloat162float(hp0->x);
        float l1 = v1 - __bfloat162float(hp0->y);
        float l2 = v2 - __bfloat162float(hp1->x);
        float l3 = v3 - __bfloat162float(hp1->y);
        lv.x = pack_bf2(l0, l1);
        lv.y = pack_bf2(l2, l3);

        size_t rb = (size_t)(3 * b + m) * K3P + 4 * j;
        *(uint2*)(g_B16 + rb)          = hv;   // seg0: hi
        *(uint2*)(g_B16 + rb + PK)     = lv;   // seg1: lo
        *(uint2*)(g_B16 + rb + 2 * PK) = hv;   // seg2: hi
    }
}

// ---------------------------------------------------------------------------
// Kernel 4: A' = Wv in bf16 hi/lo, segments [hi | hi | lo].
// ---------------------------------------------------------------------------
__global__ void wv16_kernel(const float* __restrict__ W,
                            const float* __restrict__ vt)
{
    int idx = blockIdx.x * blockDim.x + threadIdx.x;
    if (idx >= NV * 144) return;
    int v  = idx / 144;
    int k4 = idx - v * 144;

    float v0 = 0.f, v1 = 0.f, v2 = 0.f, v3 = 0.f;
    if (k4 < NJ) {
        float w = W[v * NJ + k4];
        v0 = w * vt[v * 3 + 0];
        v1 = w * vt[v * 3 + 1];
        v2 = w * vt[v * 3 + 2];
        v3 = w;
    }
    uint2 hv, lv;
    hv.x = pack_bf2(v0, v1);
    hv.y = pack_bf2(v2, v3);
    __nv_bfloat162* hp0 = reinterpret_cast<__nv_bfloat162*>(&hv.x);
    __nv_bfloat162* hp1 = reinterpret_cast<__nv_bfloat162*>(&hv.y);
    float l0 = v0 - __bfloat162float(hp0->x);
    float l1 = v1 - __bfloat162float(hp0->y);
    float l2 = v2 - __bfloat162float(hp1->x);
    float l3 = v3 - __bfloat162float(hp1->y);
    lv.x = pack_bf2(l0, l1);
    lv.y = pack_bf2(l2, l3);

    size_t base = (size_t)v * K3P + 4 * k4;
    *(uint2*)(g_A16 + base)          = hv;   // seg0: hi
    *(uint2*)(g_A16 + base + PK)     = hv;   // seg1: hi
    *(uint2*)(g_A16 + base + 2 * PK) = lv;   // seg2: lo
}

// ---------------------------------------------------------------------------
// Kernel 5: bf16 mma.sync GEMM v2.  D[128 x 192] per CTA, K = 1728.
// BK=64 (half the barriers), cp.async double buffer, register double-buffered
// ldmatrix fragments (LDS latency hidden behind HMMA issue), half-tile
// smem-staged coalesced epilogue.
// ---------------------------------------------------------------------------
__device__ __forceinline__ void load_stage(int it, uint32_t stg_base,
                                           int tid, int m0, int n0)
{
    int k0 = it * BK;
    const __nv_bfloat16* Asrc = g_A16 + (size_t)m0 * K3P + k0;
    const __nv_bfloat16* Bsrc = g_B16 + (size_t)n0 * K3P + k0;
    #pragma unroll
    for (int i = 0; i < 10; i++) {            // 2560 chunks / 256 threads
        int c = tid + i * 256;
        if (c < 1024) {                       // A: 128 rows x 8 chunks
            int row = c >> 3, seg = c & 7;
            CP16(stg_base + row * ASTRIDE + seg * 16,
                 (uint64_t)__cvta_generic_to_global(
                     (const char*)(Asrc + (size_t)row * K3P) + seg * 16));
        } else {                              // B: 192 rows x 8 chunks
            int c2 = c - 1024;
            int row = c2 >> 3, seg = c2 & 7;
            CP16(stg_base + A_SMEM + row * ASTRIDE + seg * 16,
                 (uint64_t)__cvta_generic_to_global(
                     (const char*)(Bsrc + (size_t)row * K3P) + seg * 16));
        }
    }
}

struct Frag { uint32_t a[4][4]; uint32_t b[6][2]; };

__device__ __forceinline__ void load_frags(Frag& f, uint32_t Abase, uint32_t Bbase,
                                           int ks, int a_row, int a_kof,
                                           int b_row, int b_kof)
{
    #pragma unroll
    for (int i = 0; i < 4; i++)
        ldsm4(f.a[i], Abase + (a_row + i * 16) * ASTRIDE + ks * 32 + a_kof);
    #pragma unroll
    for (int jp = 0; jp < 3; jp++) {
        uint32_t r[4];
        ldsm4(r, Bbase + (b_row + jp * 16) * ASTRIDE + ks * 32 + b_kof);
        f.b[2 * jp + 0][0] = r[0]; f.b[2 * jp + 0][1] = r[1];
        f.b[2 * jp + 1][0] = r[2]; f.b[2 * jp + 1][1] = r[3];
    }
}

__global__ __launch_bounds__(256, 1) void skin_gemm_mma(float* __restrict__ out)
{
    extern __shared__ char smem[];
    uint32_t sbase = smem_u32(smem);
    int tid = threadIdx.x;
    int wid = tid >> 5;
    int lid = tid & 31;
    int wm  = wid & 1;          // 0..1 -> 64 rows each
    int wn  = wid >> 1;         // 0..3 -> 48 cols each
    int m0  = blockIdx.x * BM;
    int n0  = blockIdx.y * BN;

    float d[4][6][4];
    #pragma unroll
    for (int i = 0; i < 4; i++)
        #pragma unroll
        for (int j = 0; j < 6; j++)
            #pragma unroll
            for (int q = 0; q < 4; q++) d[i][j][q] = 0.0f;

    load_stage(0, sbase, tid, m0, n0);
    CP_COMMIT();

    int a_row = wm * 64 + (lid & 15);
    int a_kof = (lid >> 4) * 16;
    int b_row = wn * 48 + (lid & 7) + ((lid >> 4) << 3);
    int b_kof = ((lid >> 3) & 1) * 16;

    Frag fr[2];

    for (int it = 0; it < NIT; it++) {
        uint32_t cur = sbase + (uint32_t)(it & 1) * STG;
        if (it + 1 < NIT) {
            load_stage(it + 1, sbase + (uint32_t)((it + 1) & 1) * STG, tid, m0, n0);
            CP_COMMIT();
            asm volatile("cp.async.wait_group 1;" ::: "memory");
        } else {
            asm volatile("cp.async.wait_group 0;" ::: "memory");
        }
        __syncthreads();

        uint32_t Abase = cur;
        uint32_t Bbase = cur + A_SMEM;

        load_frags(fr[0], Abase, Bbase, 0, a_row, a_kof, b_row, b_kof);
        #pragma unroll
        for (int ks = 0; ks < 4; ks++) {
            int cb = ks & 1;
            if (ks < 3)
                load_frags(fr[cb ^ 1], Abase, Bbase, ks + 1,
                           a_row, a_kof, b_row, b_kof);
            #pragma unroll
            for (int i = 0; i < 4; i++)
                #pragma unroll
                for (int j = 0; j < 6; j++)
                    mma16816(d[i][j], fr[cb].a[i], fr[cb].b[j]);
        }
        __syncthreads();
    }

    // ---- epilogue: two 64-row halves staged through smem ----
    float* Csm = (float*)smem;
    int group = lid >> 2;
    int t4    = lid & 3;
    int bb0   = blockIdx.y * 64;

    #pragma unroll
    for (int h = 0; h < 2; h++) {
        if (wm == h) {
            #pragma unroll
            for (int i = 0; i < 4; i++) {
                int r0 = i * 16 + group;            // row within half
                #pragma unroll
                for (int j = 0; j < 6; j++) {
                    int c0 = wn * 48 + j * 8 + t4 * 2;
                    Csm[r0 * CSTRIDE + c0]           = d[i][j][0];
                    Csm[r0 * CSTRIDE + c0 + 1]       = d[i][j][1];
                    Csm[(r0 + 8) * CSTRIDE + c0]     = d[i][j][2];
                    Csm[(r0 + 8) * CSTRIDE + c0 + 1] = d[i][j][3];
                }
            }
        }
        __syncthreads();
        // 64 rows x 192 cols -> out; e ordered so each warp writes a
        // contiguous 128 B run of out.
        for (int e = tid; e < 64 * 192; e += 256) {
            int bb  = e / 192;          // local batch 0..63
            int r   = e - bb * 192;     // 64 v-rows x 3 comps, contiguous in out
            int vl  = r / 3;
            int mm  = r - vl * 3;
            int v   = m0 + h * 64 + vl;
            if (v < NV)
                out[(size_t)(bb0 + bb) * (NV * 3) + v * 3 + mm] =
                    Csm[vl * CSTRIDE + bb * 3 + mm];
        }
        __syncthreads();
    }
}

// ---------------------------------------------------------------------------
// Launch
// ---------------------------------------------------------------------------
extern "C" void kernel_launch(void* const* d_in, const int* in_sizes, int n_in,
                              void* d_out, int out_size)
{
    const float* pose        = (const float*)d_in[0];
    const float* bone_len    = (const float*)d_in[1];
    const float* cbl         = (const float*)d_in[2];
    const float* trans       = (const float*)d_in[3];
    const float* scale       = (const float*)d_in[4];
    const float* v_template  = (const float*)d_in[5];
    const float* tpj         = (const float*)d_in[6];
    const float* weights     = (const float*)d_in[7];
    const int*   parent      = (const int*)d_in[8];
    const int*   bone_mapper = (const int*)d_in[9];

    float* out  = (float*)d_out;
    float* jout = out + (size_t)BATCH * NV * 3;   // V first, then J_out

    int bj = BATCH * NJ;
    rot_kernel<<<(bj + 255) / 256, 256>>>(pose, bone_len, cbl, tpj,
                                          parent, bone_mapper);

    int nblk = (BATCH + CHAIN_BPB - 1) / CHAIN_BPB;
    chain_kernel<<<nblk, 32>>>(parent);

    bt16_kernel<<<(bj + 255) / 256, 256>>>(tpj, trans, scale, jout);

    int wvt = NV * 144;
    wv16_kernel<<<(wvt + 255) / 256, 256>>>(weights, v_template);

    cudaFuncSetAttribute(skin_gemm_mma,
                         cudaFuncAttributeMaxDynamicSharedMemorySize,
                         GEMM_SMEM_BYTES);
    dim3 grid(MP / BM, NCOLS / BN);   // 103 x 8
    skin_gemm_mma<<<grid, 256, GEMM_SMEM_BYTES>>>(out);
}

// round 12
// speedup vs baseline: 5.1629x; 1.2262x over previous
#include <cuda_runtime.h>
#include <cuda_bf16.h>
#include <math.h>
#include <stdint.h>

#define NJ     140
#define NV     13059
#define NB     28
#define BATCH  512
#define NCOLS  (BATCH * 3)       // 1536
#define PK     576               // padded K per segment
#define K2P    (2 * PK)          // 1152 stored K (hi|lo)
#define MP     13248             // padded M (69 * 192)
#define BM     192
#define BN     192               // multiple of 3 -> 64 whole batches per tile
#define BK     64                // K elems per mainloop iter (128 B/row)
#define NIT    27                // 3 segments x 9 iters
#define ASTRIDE 144              // bytes per smem row (128 data + 16 pad)
#define A_SMEM  (BM * ASTRIDE)   // 27648
#define B_SMEM  (BN * ASTRIDE)   // 27648
#define STG     (A_SMEM + B_SMEM)// 55296
#define NSTAGE 3
#define CSTRIDE 195              // floats, C staging row stride (64-row half)
#define GEMM_SMEM_BYTES (NSTAGE * STG)  // 165888

// Static device scratch (zero-initialized; pad regions never written => stay 0)
__device__ float4        g_R4[NJ * BATCH * 3];
__device__ float4        g_H4[NJ * BATCH * 3];
__device__ __nv_bfloat16 g_A16[(size_t)MP * K2P];     // A' [13248 x 1152] = [hi|lo]
__device__ __nv_bfloat16 g_B16[(size_t)NCOLS * K2P];  // B' [1536 x 1152] = [bh|bl]

// ---------------------------------------------------------------------------
// helpers
// ---------------------------------------------------------------------------
__device__ __forceinline__ uint32_t smem_u32(const void* p) {
    uint32_t a;
    asm("{ .reg .u64 t; cvta.to.shared.u64 t, %1; cvt.u32.u64 %0, t; }"
        : "=r"(a) : "l"(p));
    return a;
}
#define CP16(dst, src) \
    asm volatile("cp.async.cg.shared.global [%0], [%1], 16;" \
                 :: "r"(dst), "l"(src) : "memory")
#define CP_COMMIT() asm volatile("cp.async.commit_group;" ::: "memory")

__device__ __forceinline__ uint32_t pack_bf2(float a, float b) {
    __nv_bfloat162 h = __floats2bfloat162_rn(a, b);
    return *reinterpret_cast<uint32_t*>(&h);
}

__device__ __forceinline__ void ldsm4(uint32_t* r, uint32_t addr) {
    asm volatile("ldmatrix.sync.aligned.m8n8.x4.shared.b16 {%0,%1,%2,%3}, [%4];"
                 : "=r"(r[0]), "=r"(r[1]), "=r"(r[2]), "=r"(r[3]) : "r"(addr));
}
__device__ __forceinline__ void mma16816(float* d, const uint32_t* a,
                                         const uint32_t* b) {
    asm volatile(
        "mma.sync.aligned.m16n8k16.row.col.f32.bf16.bf16.f32 "
        "{%0,%1,%2,%3}, {%4,%5,%6,%7}, {%8,%9}, {%0,%1,%2,%3};"
        : "+f"(d[0]), "+f"(d[1]), "+f"(d[2]), "+f"(d[3])
        : "r"(a[0]), "r"(a[1]), "r"(a[2]), "r"(a[3]), "r"(b[0]), "r"(b[1]));
}

// ---------------------------------------------------------------------------
// Kernel 1: rotations + scaled bone offsets. One thread per (b, j).
// q0=(R00,R01,R02,R10) q1=(R11,R12,R20,R21) q2=(R22,o0,o1,o2)
// ---------------------------------------------------------------------------
__global__ void rot_kernel(const float* __restrict__ pose,
                           const float* __restrict__ bone_len,
                           const float* __restrict__ cbl_in,
                           const float* __restrict__ tpj,
                           const int*   __restrict__ parent,
                           const int*   __restrict__ bone_mapper)
{
    int idx = blockIdx.x * blockDim.x + threadIdx.x;
    if (idx >= BATCH * NJ) return;
    int b = idx / NJ;
    int j = idx - b * NJ;

    float ez = pose[b * NJ * 3 + j * 3 + 0];
    float ey = pose[b * NJ * 3 + j * 3 + 1];
    float ex = pose[b * NJ * 3 + j * 3 + 2];
    float cx, sx, cy, sy, cz, sz;
    sincosf(ex, &sx, &cx);
    sincosf(ey, &sy, &cy);
    sincosf(ez, &sz, &cz);
    float R0 = cz * cy;
    float R1 = cz * sy * sx - sz * cx;
    float R2 = cz * sy * cx + sz * sx;
    float R3 = sz * cy;
    float R4 = sz * sy * sx + cz * cx;
    float R5 = sz * sy * cx - cz * sx;
    float R6 = -sy;
    float R7 = cy * sx;
    float R8 = cy * cx;

    float o0, o1, o2;
    if (j == 0) {
        o0 = tpj[0]; o1 = tpj[1]; o2 = tpj[2];
    } else {
        int p = parent[j];
        float f;
        if (j == 1) {
            f = cbl_in[b];
        } else {
            int bm = bone_mapper[j];
            f = (bm >= 0) ? (2.0f / (1.0f + expf(-bone_len[b * NB + bm] * 0.2f)))
                          : 1.0f;
        }
        o0 = (tpj[j * 3 + 0] - tpj[p * 3 + 0]) * f;
        o1 = (tpj[j * 3 + 1] - tpj[p * 3 + 1]) * f;
        o2 = (tpj[j * 3 + 2] - tpj[p * 3 + 2]) * f;
    }

    size_t o = (size_t)(j * BATCH + b) * 3;
    g_R4[o + 0] = make_float4(R0, R1, R2, R3);
    g_R4[o + 1] = make_float4(R4, R5, R6, R7);
    g_R4[o + 2] = make_float4(R8, o0, o1, o2);
}

// ---------------------------------------------------------------------------
// Kernel 2: kinematic chain (round-4 passing version, unchanged).
// ---------------------------------------------------------------------------
#define CHAIN_BPB 7
__global__ __launch_bounds__(32, 1) void chain_kernel(const int* __restrict__ parent)
{
    __shared__ float4 sh[CHAIN_BPB * 3 * NJ];
    __shared__ int    sPar[NJ];

    for (int i = threadIdx.x; i < NJ; i += blockDim.x) sPar[i] = parent[i];
    __syncthreads();

    int local = threadIdx.x;
    if (local >= CHAIN_BPB * 3) return;
    int lb = local / 3;
    int r  = local - lb * 3;
    int b  = blockIdx.x * CHAIN_BPB + lb;
    if (b >= BATCH) return;

    const size_t stride = (size_t)BATCH * 3;
    const float4* Rb = g_R4 + (size_t)b * 3;
    float4* myhist = sh + (size_t)local * NJ;

    float4 q0 = Rb[0], q1 = Rb[1], q2 = Rb[2];
    float4 row;
    if (r == 0)      row = make_float4(q0.x, q0.y, q0.z, q2.y);
    else if (r == 1) row = make_float4(q0.w, q1.x, q1.y, q2.z);
    else             row = make_float4(q1.z, q1.w, q2.x, q2.w);
    myhist[0] = row;
    g_H4[(size_t)0 * stride + b * 3 + r] = row;

    float4 n0 = Rb[stride + 0];
    float4 n1 = Rb[stride + 1];
    float4 n2 = Rb[stride + 2];

    for (int j = 1; j < NJ; j++) {
        q0 = n0; q1 = n1; q2 = n2;
        if (j < NJ - 1) {
            n0 = Rb[(size_t)(j + 1) * stride + 0];
            n1 = Rb[(size_t)(j + 1) * stride + 1];
            n2 = Rb[(size_t)(j + 1) * stride + 2];
        }
        float4 hp = myhist[sPar[j]];
        float nr0 = hp.x * q0.x + hp.y * q0.w + hp.z * q1.z;
        float nr1 = hp.x * q0.y + hp.y * q1.x + hp.z * q1.w;
        float nr2 = hp.x * q0.z + hp.y * q1.y + hp.z * q2.x;
        float nr3 = hp.x * q2.y + hp.y * q2.z + hp.z * q2.w + hp.w;
        float4 nrow = make_float4(nr0, nr1, nr2, nr3);
        myhist[j] = nrow;
        g_H4[(size_t)j * stride + b * 3 + r] = nrow;
    }
}

// ---------------------------------------------------------------------------
// Kernel 3: G_rel fold -> g_B16 (bf16 hi/lo, [bh | bl]) + jout.
// ---------------------------------------------------------------------------
__global__ void bt16_kernel(const float* __restrict__ tpj,
                            const float* __restrict__ trans,
                            const float* __restrict__ scale,
                            float*       __restrict__ jout)
{
    int idx = blockIdx.x * blockDim.x + threadIdx.x;
    if (idx >= BATCH * NJ) return;
    int b = idx & (BATCH - 1);
    int j = idx >> 9;

    size_t base = (size_t)j * BATCH * 3 + b * 3;
    float4 h0 = g_H4[base + 0];
    float4 h1 = g_H4[base + 1];
    float4 h2 = g_H4[base + 2];

    float s   = scale[b];
    float tr0 = trans[b * 3 + 0];
    float tr1 = trans[b * 3 + 1];
    float tr2 = trans[b * 3 + 2];
    float jx = tpj[j * 3 + 0], jy = tpj[j * 3 + 1], jz = tpj[j * 3 + 2];

    jout[b * NJ * 3 + j * 3 + 0] = h0.w * s + tr0;
    jout[b * NJ * 3 + j * 3 + 1] = h1.w * s + tr1;
    jout[b * NJ * 3 + j * 3 + 2] = h2.w * s + tr2;

    float gt0 = h0.w - (h0.x * jx + h0.y * jy + h0.z * jz);
    float gt1 = h1.w - (h1.x * jx + h1.y * jy + h1.z * jz);
    float gt2 = h2.w - (h2.x * jx + h2.y * jy + h2.z * jz);

    #pragma unroll
    for (int m = 0; m < 3; m++) {
        float4 h  = (m == 0) ? h0 : (m == 1) ? h1 : h2;
        float  gt = (m == 0) ? gt0 : (m == 1) ? gt1 : gt2;
        float  tr = (m == 0) ? tr0 : (m == 1) ? tr1 : tr2;
        float v0 = h.x * s, v1 = h.y * s, v2 = h.z * s, v3 = gt * s + tr;

        uint2 hv, lv;
        hv.x = pack_bf2(v0, v1);
        hv.y = pack_bf2(v2, v3);
        __nv_bfloat162* hp0 = reinterpret_cast<__nv_bfloat162*>(&hv.x);
        __nv_bfloat162* hp1 = reinterpret_cast<__nv_bfloat162*>(&hv.y);
        float l0 = v0 - __bfloat162float(hp0->x);
        float l1 = v1 - __bfloat162float(hp0->y);
        float l2 = v2 - __bfloat162float(hp1->x);
        float l3 = v3 - __bfloat162float(hp1->y);
        lv.x = pack_bf2(l0, l1);
        lv.y = pack_bf2(l2, l3);

        size_t rb = (size_t)(3 * b + m) * K2P + 4 * j;
        *(uint2*)(g_B16 + rb)      = hv;   // bh
        *(uint2*)(g_B16 + rb + PK) = lv;   // bl
    }
}

// ---------------------------------------------------------------------------
// Kernel 4: A' = Wv in bf16 hi/lo, [hi | lo].
// ---------------------------------------------------------------------------
__global__ void wv16_kernel(const float* __restrict__ W,
                            const float* __restrict__ vt)
{
    int idx = blockIdx.x * blockDim.x + threadIdx.x;
    if (idx >= NV * 144) return;
    int v  = idx / 144;
    int k4 = idx - v * 144;

    float v0 = 0.f, v1 = 0.f, v2 = 0.f, v3 = 0.f;
    if (k4 < NJ) {
        float w = W[v * NJ + k4];
        v0 = w * vt[v * 3 + 0];
        v1 = w * vt[v * 3 + 1];
        v2 = w * vt[v * 3 + 2];
        v3 = w;
    }
    uint2 hv, lv;
    hv.x = pack_bf2(v0, v1);
    hv.y = pack_bf2(v2, v3);
    __nv_bfloat162* hp0 = reinterpret_cast<__nv_bfloat162*>(&hv.x);
    __nv_bfloat162* hp1 = reinterpret_cast<__nv_bfloat162*>(&hv.y);
    float l0 = v0 - __bfloat162float(hp0->x);
    float l1 = v1 - __bfloat162float(hp0->y);
    float l2 = v2 - __bfloat162float(hp1->x);
    float l3 = v3 - __bfloat162float(hp1->y);
    lv.x = pack_bf2(l0, l1);
    lv.y = pack_bf2(l2, l3);

    size_t base = (size_t)v * K2P + 4 * k4;
    *(uint2*)(g_A16 + base)      = hv;   // hi
    *(uint2*)(g_A16 + base + PK) = lv;   // lo
}

// ---------------------------------------------------------------------------
// Kernel 5: bf16 mma.sync GEMM v3b.  D[192 x 192] per CTA, 384 threads.
// 27 iters = 3 segments x 9: seg0 Ah*Bh, seg1 Ah*Bl, seg2 Al*Bh (dedup'd
// storage, sources remapped). 3-stage cp.async ring.
// RACE FIX vs round 9: prefetch of stage (it+2)%3 is issued AFTER the
// iteration barrier, so buffer (it-1)%3 is only overwritten once every warp
// has finished reading it.
// ---------------------------------------------------------------------------
__device__ __forceinline__ void load_stage(int it, uint32_t stg_base,
                                           int tid, int m0, int n0)
{
    int seg = (it < 9) ? 0 : (it < 18 ? 1 : 2);
    int off = (it - seg * 9) * BK;
    int kA  = off + (seg == 2 ? PK : 0);   // seg2 reads A-lo
    int kB  = off + (seg == 1 ? PK : 0);   // seg1 reads B-lo
    const __nv_bfloat16* Asrc = g_A16 + (size_t)m0 * K2P + kA;
    const __nv_bfloat16* Bsrc = g_B16 + (size_t)n0 * K2P + kB;
    #pragma unroll
    for (int i = 0; i < 8; i++) {             // 3072 chunks / 384 threads
        int c = tid + i * 384;
        if (c < 1536) {                       // A: 192 rows x 8 chunks
            int row = c >> 3, sg = c & 7;
            CP16(stg_base + row * ASTRIDE + sg * 16,
                 (uint64_t)__cvta_generic_to_global(
                     (const char*)(Asrc + (size_t)row * K2P) + sg * 16));
        } else {                              // B: 192 rows x 8 chunks
            int c2 = c - 1536;
            int row = c2 >> 3, sg = c2 & 7;
            CP16(stg_base + A_SMEM + row * ASTRIDE + sg * 16,
                 (uint64_t)__cvta_generic_to_global(
                     (const char*)(Bsrc + (size_t)row * K2P) + sg * 16));
        }
    }
}

__global__ __launch_bounds__(384, 1) void skin_gemm_mma(float* __restrict__ out)
{
    extern __shared__ char smem[];
    uint32_t sbase = smem_u32(smem);
    int tid = threadIdx.x;
    int wid = tid >> 5;
    int lid = tid & 31;
    int wm  = wid >> 2;         // 0..2 -> 64 rows each
    int wn  = wid & 3;          // 0..3 -> 48 cols each
    int m0  = blockIdx.x * BM;
    int n0  = blockIdx.y * BN;

    float d[4][6][4];
    #pragma unroll
    for (int i = 0; i < 4; i++)
        #pragma unroll
        for (int j = 0; j < 6; j++)
            #pragma unroll
            for (int q = 0; q < 4; q++) d[i][j][q] = 0.0f;

    load_stage(0, sbase, tid, m0, n0);
    CP_COMMIT();
    load_stage(1, sbase + STG, tid, m0, n0);
    CP_COMMIT();

    int a_row = wm * 64 + (lid & 15);
    int a_kof = (lid >> 4) * 16;
    int b_row = wn * 48 + (lid & 7) + ((lid >> 4) << 3);
    int b_kof = ((lid >> 3) & 1) * 16;

    for (int it = 0; it < NIT; it++) {
        // stage `it` must be resident: pending groups are {it, it+1}
        if (it + 1 < NIT)
            asm volatile("cp.async.wait_group 1;" ::: "memory");
        else
            asm volatile("cp.async.wait_group 0;" ::: "memory");
        __syncthreads();

        // prefetch AFTER the barrier: buffer (it+2)%3 == (it-1)%3 is now free
        if (it + 2 < NIT) {
            load_stage(it + 2, sbase + (uint32_t)((it + 2) % 3) * STG,
                       tid, m0, n0);
            CP_COMMIT();
        }

        uint32_t cur   = sbase + (uint32_t)(it % 3) * STG;
        uint32_t Abase = cur;
        uint32_t Bbase = cur + A_SMEM;

        #pragma unroll
        for (int ks = 0; ks < 4; ks++) {
            uint32_t af[4][4], bf[6][2];
            #pragma unroll
            for (int i = 0; i < 4; i++)
                ldsm4(af[i], Abase + (a_row + i * 16) * ASTRIDE + ks * 32 + a_kof);
            #pragma unroll
            for (int jp = 0; jp < 3; jp++) {
                uint32_t r[4];
                ldsm4(r, Bbase + (b_row + jp * 16) * ASTRIDE + ks * 32 + b_kof);
                bf[2 * jp + 0][0] = r[0]; bf[2 * jp + 0][1] = r[1];
                bf[2 * jp + 1][0] = r[2]; bf[2 * jp + 1][1] = r[3];
            }
            #pragma unroll
            for (int i = 0; i < 4; i++)
                #pragma unroll
                for (int j = 0; j < 6; j++)
                    mma16816(d[i][j], af[i], bf[j]);
        }
    }

    // ---- epilogue: three 64-row groups staged through smem ----
    // Csm (49920 B) lies inside stage-0+1 buffers; last compute used stage 2
    // only at it=26, and every warp passed it=26's barrier, so stages 0/1 are
    // no longer being read. First __syncthreads below orders writes anyway.
    float* Csm = (float*)smem;
    int group = lid >> 2;
    int t4    = lid & 3;
    int bb0   = blockIdx.y * 64;

    __syncthreads();   // all warps done with mainloop reads before Csm writes
    #pragma unroll
    for (int h = 0; h < 3; h++) {
        if (wm == h) {
            #pragma unroll
            for (int i = 0; i < 4; i++) {
                int r0 = i * 16 + group;
                #pragma unroll
                for (int j = 0; j < 6; j++) {
                    int c0 = wn * 48 + j * 8 + t4 * 2;
                    Csm[r0 * CSTRIDE + c0]           = d[i][j][0];
                    Csm[r0 * CSTRIDE + c0 + 1]       = d[i][j][1];
                    Csm[(r0 + 8) * CSTRIDE + c0]     = d[i][j][2];
                    Csm[(r0 + 8) * CSTRIDE + c0 + 1] = d[i][j][3];
                }
            }
        }
        __syncthreads();
        for (int e = tid; e < 64 * 192; e += 384) {
            int bb  = e / 192;          // local batch 0..63
            int r   = e - bb * 192;
            int vl  = r / 3;
            int mm  = r - vl * 3;
            int v   = m0 + h * 64 + vl;
            if (v < NV)
                out[(size_t)(bb0 + bb) * (NV * 3) + v * 3 + mm] =
                    Csm[vl * CSTRIDE + bb * 3 + mm];
        }
        __syncthreads();
    }
}

// ---------------------------------------------------------------------------
// Launch
// ---------------------------------------------------------------------------
extern "C" void kernel_launch(void* const* d_in, const int* in_sizes, int n_in,
                              void* d_out, int out_size)
{
    const float* pose        = (const float*)d_in[0];
    const float* bone_len    = (const float*)d_in[1];
    const float* cbl         = (const float*)d_in[2];
    const float* trans       = (const float*)d_in[3];
    const float* scale       = (const float*)d_in[4];
    const float* v_template  = (const float*)d_in[5];
    const float* tpj         = (const float*)d_in[6];
    const float* weights     = (const float*)d_in[7];
    const int*   parent      = (const int*)d_in[8];
    const int*   bone_mapper = (const int*)d_in[9];

    float* out  = (float*)d_out;
    float* jout = out + (size_t)BATCH * NV * 3;   // V first, then J_out

    int bj = BATCH * NJ;
    rot_kernel<<<(bj + 255) / 256, 256>>>(pose, bone_len, cbl, tpj,
                                          parent, bone_mapper);

    int nblk = (BATCH + CHAIN_BPB - 1) / CHAIN_BPB;
    chain_kernel<<<nblk, 32>>>(parent);

    bt16_kernel<<<(bj + 255) / 256, 256>>>(tpj, trans, scale, jout);

    int wvt = NV * 144;
    wv16_kernel<<<(wvt + 255) / 256, 256>>>(weights, v_template);

    cudaFuncSetAttribute(skin_gemm_mma,
                         cudaFuncAttributeMaxDynamicSharedMemorySize,
                         GEMM_SMEM_BYTES);
    dim3 grid(MP / BM, NCOLS / BN);   // 69 x 8
    skin_gemm_mma<<<grid, 384, GEMM_SMEM_BYTES>>>(out);
}